// round 11
// baseline (speedup 1.0000x reference)
#include <cuda_runtime.h>
#include <cuda_fp16.h>
#include <cstdint>

// PIPNet fused gather + MLP via mma.sync (HMMA) fp16, persistent-B.
//   out[p] = relu(concat(g1[il[p]], g2[ir[p]]) @ W1^T + b1) @ W2^T + b2
//
// R10: B-fragment LDG was 60% of the binding l1tex pipe (L1=66.8%). Each
// warp now owns a fixed 32-wide N slice and keeps its ENTIRE B operand
// (32n x 128k fp16 fragments = 64 regs) in registers, loaded once. CTAs are
// persistent over 32-pair M-tiles (grid-stride) with double-buffered A and
// software-pipelined gather (next tile's LDGs issued before this tile's MMAs).

#define MROWS 32        // pairs per tile
#define NTHREADS 256
#define GRID_CTAS 1480

// smem layout (bytes)
#define SM_A0   0               // A tile buf0: 32 x 128 fp16 = 8KB
#define SM_A1   8192            // A tile buf1
#define SM_B1   16384           // b1[128] f32
#define SM_W2   16896           // W2[128] f32
#define SM_RED  17408           // red[32][4] f32
#define SMEM_TOTAL (17920 + 128)

// W1 fp16 fragment buffer: [nb(2)][ks(8)][pr(4)][lane(32)][reg(4)] u32 = 32KB.
__device__ uint32_t g_Wfrag[2 * 8 * 4 * 32 * 4];

static __device__ __forceinline__ uint32_t smem_u32(const void* p) {
    uint32_t a;
    asm("{ .reg .u64 t; cvta.to.shared.u64 t, %1; cvt.u32.u64 %0, t; }"
        : "=r"(a) : "l"(p));
    return a;
}

// Byte offset into the 32x128 fp16 A tile: rows 256B, 16B chunks xor-swizzled.
static __device__ __forceinline__ uint32_t tile_off(int row, int chunk) {
    return (uint32_t)row * 256u + (uint32_t)((chunk ^ (row & 7)) * 16);
}

static __device__ __forceinline__ void ldsm_x4(uint32_t* r, uint32_t addr) {
    asm volatile("ldmatrix.sync.aligned.m8n8.x4.shared.b16 {%0,%1,%2,%3}, [%4];"
                 : "=r"(r[0]), "=r"(r[1]), "=r"(r[2]), "=r"(r[3]) : "r"(addr));
}
static __device__ __forceinline__ void mma_f16(float* c, const uint32_t* a,
                                               uint32_t b0, uint32_t b1) {
    asm volatile("mma.sync.aligned.m16n8k16.row.col.f32.f16.f16.f32 "
                 "{%0,%1,%2,%3}, {%4,%5,%6,%7}, {%8,%9}, {%0,%1,%2,%3};"
                 : "+f"(c[0]), "+f"(c[1]), "+f"(c[2]), "+f"(c[3])
                 : "r"(a[0]), "r"(a[1]), "r"(a[2]), "r"(a[3]), "r"(b0), "r"(b1));
}

static __device__ __forceinline__ uint32_t pack_h2(__half a, __half b) {
    __half2 h = __halves2half2(a, b);
    return *(uint32_t*)&h;
}

// ---- Prep: write W1's fp16 mma B-fragments in fragment order ----
// NON-trans ldmatrix x4 reg j at lane l holds the f16x2 pair
// W1h[n][k], W1h[n][k+1] with
//   n = nb*64 + pr*16 + (j>>1)*8 + (l>>2),  k = ks*16 + (j&1)*8 + 2*(l&3).
__global__ void pipnet_prep_wfrag(const float* __restrict__ W1) {
    int flat = blockIdx.x * blockDim.x + threadIdx.x;   // 8192 entries
    if (flat >= 8192) return;
    int j  = flat & 3;
    int l  = (flat >> 2) & 31;
    int pr = (flat >> 7) & 3;
    int ks = (flat >> 9) & 7;
    int nb = (flat >> 12) & 1;
    int n = nb * 64 + pr * 16 + ((j >> 1) << 3) + (l >> 2);
    int k = ks * 16 + ((j & 1) << 3) + 2 * (l & 3);
    g_Wfrag[flat] = pack_h2(__float2half_rn(W1[n * 128 + k]),
                            __float2half_rn(W1[n * 128 + k + 1]));
}

__global__ __launch_bounds__(NTHREADS, 2)
void pipnet_hmma_kernel(const float* __restrict__ g1,
                        const float* __restrict__ g2,
                        const int* __restrict__ idxL,
                        const int* __restrict__ idxR,
                        const float* __restrict__ b1,
                        const float* __restrict__ W2,
                        const float* __restrict__ b2,
                        float* __restrict__ out,
                        int P, int Nnodes)
{
    extern __shared__ char smem[];
    const uint32_t sbase = smem_u32(smem);
    const int tid = threadIdx.x;
    const int wid = tid >> 5;
    const int lid = tid & 31;
    const int wm = wid >> 2;            // m-group (0-1): rows wm*16..+15
    const int wn = wid & 3;             // n-group (0-3): cols wn*32..+31
    const int gl = lid & 7;
    const int grp = lid >> 3;
    const int lane_in = lid & 15;       // float4 slot within a node row

    const int numTiles = (P + MROWS - 1) / MROWS;

    // ---- Stage b1 / W2 ----
    if (tid < 128) {
        *(float*)(smem + SM_B1 + tid * 4) = b1[tid];
        *(float*)(smem + SM_W2 + tid * 4) = W2[tid];
    }
    const float b2v = b2[0];

    // ---- Load persistent B fragments: 32n x 128k in 64 regs ----
    const int nb = wn >> 1;
    const int pr0 = (wn & 1) * 2;
    uint4 bA[8], bB[8];
    {
        const uint4* __restrict__ Wf = (const uint4*)g_Wfrag;
        #pragma unroll
        for (int ks = 0; ks < 8; ++ks) {
            const uint4* wk = Wf + ((nb * 8 + ks) * 4) * 32 + lid;
            bA[ks] = wk[pr0 * 32];
            bB[ks] = wk[(pr0 + 1) * 32];
        }
    }

    // ---- Gather addressing (tile-invariant parts) ----
    // Warp handles rowhalves rh = wid*8 + jj*2 + (lid>>4), jj in 0..3.
    int rr[4], hh[4];
    uint32_t soff[4];
    #pragma unroll
    for (int jj = 0; jj < 4; ++jj) {
        int rh = wid * 8 + jj * 2 + (lid >> 4);
        rr[jj] = rh & 31;
        hh[jj] = rh >> 5;
        soff[jj] = tile_off(rr[jj], hh[jj] * 8 + (lane_in >> 1)) + (lane_in & 1) * 8;
    }

    const float* s_b1 = (const float*)(smem + SM_B1);
    const float* s_w2 = (const float*)(smem + SM_W2);
    float* red = (float*)(smem + SM_RED);

    int t = blockIdx.x;
    if (t >= numTiles) return;

    // ---- Gather helper (to regs) ----
    uint2 hv[4];
    auto gather_regs = [&](int tt) {
        #pragma unroll
        for (int jj = 0; jj < 4; ++jj) {
            long long pair = (long long)tt * MROWS + rr[jj];
            if (pair >= P) pair = P - 1;
            int srcRow = hh[jj] ? idxR[pair] : idxL[pair];
            if (srcRow < 0) srcRow = 0;
            if (srcRow >= Nnodes) srcRow = Nnodes - 1;
            const float4* src =
                (const float4*)((hh[jj] ? g2 : g1) + (long long)srcRow * 64);
            float4 v = src[lane_in];
            hv[jj] = make_uint2(pack_h2(__float2half_rn(v.x), __float2half_rn(v.y)),
                                pack_h2(__float2half_rn(v.z), __float2half_rn(v.w)));
        }
    };

    // ---- Prologue: tile t into buf0 ----
    gather_regs(t);
    #pragma unroll
    for (int jj = 0; jj < 4; ++jj)
        *(uint2*)(smem + SM_A0 + soff[jj]) = hv[jj];
    __syncthreads();

    int it = 0;
    while (true) {
        int tn = t + GRID_CTAS;
        bool have_next = tn < numTiles;
        if (have_next) gather_regs(tn);        // LDGs in flight during MMA

        // ---- Compute current tile from buf[it&1] ----
        const uint32_t aT = sbase + ((it & 1) ? SM_A1 : SM_A0);
        float acc[4][4];
        #pragma unroll
        for (int c = 0; c < 4; ++c)
            #pragma unroll
            for (int q = 0; q < 4; ++q) acc[c][q] = 0.f;

        #pragma unroll
        for (int ks = 0; ks < 8; ++ks) {
            uint32_t af[4];
            int row = wm * 16 + (grp & 1) * 8 + gl;
            ldsm_x4(af, aT + tile_off(row, ks * 2 + (grp >> 1)));
            mma_f16(acc[0], af, bA[ks].x, bA[ks].y);
            mma_f16(acc[1], af, bA[ks].z, bA[ks].w);
            mma_f16(acc[2], af, bB[ks].x, bB[ks].y);
            mma_f16(acc[3], af, bB[ks].z, bB[ks].w);
        }

        // ---- Epilogue: bias + ReLU + W2 dot, quad-reduce, stage partials ----
        float pa = 0.f, pb = 0.f;   // rows wm*16+(lid>>2) and +8
        #pragma unroll
        for (int c = 0; c < 4; ++c) {
            int n = wn * 32 + c * 8 + 2 * (lid & 3);
            float b0 = s_b1[n], b1x = s_b1[n + 1];
            float w0 = s_w2[n], w1x = s_w2[n + 1];
            pa += fmaxf(acc[c][0] + b0, 0.f) * w0 + fmaxf(acc[c][1] + b1x, 0.f) * w1x;
            pb += fmaxf(acc[c][2] + b0, 0.f) * w0 + fmaxf(acc[c][3] + b1x, 0.f) * w1x;
        }
        pa += __shfl_xor_sync(0xffffffffu, pa, 1);
        pa += __shfl_xor_sync(0xffffffffu, pa, 2);
        pb += __shfl_xor_sync(0xffffffffu, pb, 1);
        pb += __shfl_xor_sync(0xffffffffu, pb, 2);
        if ((lid & 3) == 0) {
            int ra = wm * 16 + (lid >> 2);
            red[ra * 4 + wn] = pa;
            red[(ra + 8) * 4 + wn] = pb;
        }
        __syncthreads();

        // ---- Write outputs for tile t; stage next A tile ----
        if (tid < MROWS) {
            float4 v = ((const float4*)red)[tid];
            long long p = (long long)t * MROWS + tid;
            if (p < P) out[p] = v.x + v.y + v.z + v.w + b2v;
        }
        if (!have_next) break;
        {
            char* dst = smem + ((it & 1) ? SM_A0 : SM_A1);
            #pragma unroll
            for (int jj = 0; jj < 4; ++jj)
                *(uint2*)(dst + soff[jj]) = hv[jj];
        }
        __syncthreads();
        t = tn;
        ++it;
    }
}

extern "C" void kernel_launch(void* const* d_in, const int* in_sizes, int n_in,
                              void* d_out, int out_size) {
    const float* g1  = (const float*)d_in[0];   // graph1_x [N,64]
    const float* g2  = (const float*)d_in[1];   // graph2_x [N,64]
    const int*   il  = (const int*)d_in[2];     // idx_left  [P] int32
    const int*   ir  = (const int*)d_in[3];     // idx_right [P] int32
    const float* W1  = (const float*)d_in[4];   // [128,128]
    const float* b1  = (const float*)d_in[5];   // [128]
    const float* W2  = (const float*)d_in[6];   // [1,128]
    const float* b2  = (const float*)d_in[7];   // [1]
    float*       out = (float*)d_out;           // [P,1]

    int P = in_sizes[2];
    int Nnodes = in_sizes[0] / 64;
    int numTiles = (P + MROWS - 1) / MROWS;
    int grid = numTiles < GRID_CTAS ? numTiles : GRID_CTAS;

    pipnet_prep_wfrag<<<32, 256>>>(W1);

    cudaFuncSetAttribute(pipnet_hmma_kernel,
                         cudaFuncAttributeMaxDynamicSharedMemorySize, SMEM_TOTAL);
    pipnet_hmma_kernel<<<grid, NTHREADS, SMEM_TOTAL>>>(
        g1, g2, il, ir, b1, W2, b2, out, P, Nnodes);
}

// round 12
// speedup vs baseline: 1.3215x; 1.3215x over previous
#include <cuda_runtime.h>
#include <cuda_fp16.h>
#include <cstdint>

// PIPNet fused gather + MLP via mma.sync (HMMA) single-fp16.
//   out[p] = relu(concat(g1[il[p]], g2[ir[p]]) @ W1^T + b1) @ W2^T + b2
//
// R11: R10 (persistent-B) regressed -- killing B traffic cost occupancy and
// ILP. Revert to R9's simple one-tile-per-CTA shape but amortize B over 2x
// the rows: MTILE=128, warp tile 32m x 64n. B LDG per output halves vs R9
// (l1tex was the binding pipe at 66.8%); tensor work unchanged.

#define MTILE 128
#define NTHREADS 256

// smem layout (bytes): A tile 128x128 fp16 (rows 256B, swizzled 16B chunks).
#define SM_A    0
#define SM_B1   32768
#define SM_W2   33280
#define SM_RED  33792
#define SMEM_TOTAL (33792 + 1024 + 128)

// W1 fp16 fragment buffer: [nb(2)][ks(8)][pr(4)][lane(32)][reg(4)] u32 = 32KB.
__device__ uint32_t g_Wfrag[2 * 8 * 4 * 32 * 4];

static __device__ __forceinline__ uint32_t smem_u32(const void* p) {
    uint32_t a;
    asm("{ .reg .u64 t; cvta.to.shared.u64 t, %1; cvt.u32.u64 %0, t; }"
        : "=r"(a) : "l"(p));
    return a;
}

static __device__ __forceinline__ uint32_t tile_off(int row, int chunk) {
    return (uint32_t)row * 256u + (uint32_t)((chunk ^ (row & 7)) * 16);
}

static __device__ __forceinline__ void ldsm_x4(uint32_t* r, uint32_t addr) {
    asm volatile("ldmatrix.sync.aligned.m8n8.x4.shared.b16 {%0,%1,%2,%3}, [%4];"
                 : "=r"(r[0]), "=r"(r[1]), "=r"(r[2]), "=r"(r[3]) : "r"(addr));
}
static __device__ __forceinline__ void mma_f16(float* c, const uint32_t* a,
                                               uint32_t b0, uint32_t b1) {
    asm volatile("mma.sync.aligned.m16n8k16.row.col.f32.f16.f16.f32 "
                 "{%0,%1,%2,%3}, {%4,%5,%6,%7}, {%8,%9}, {%0,%1,%2,%3};"
                 : "+f"(c[0]), "+f"(c[1]), "+f"(c[2]), "+f"(c[3])
                 : "r"(a[0]), "r"(a[1]), "r"(a[2]), "r"(a[3]), "r"(b0), "r"(b1));
}

static __device__ __forceinline__ uint32_t pack_h2(__half a, __half b) {
    __half2 h = __halves2half2(a, b);
    return *(uint32_t*)&h;
}

// ---- Prep: write W1's fp16 mma B-fragments in fragment order ----
// NON-trans ldmatrix x4 reg j at lane l holds the f16x2 pair
// W1h[n][k], W1h[n][k+1] with
//   n = nb*64 + pr*16 + (j>>1)*8 + (l>>2),  k = ks*16 + (j&1)*8 + 2*(l&3).
__global__ void pipnet_prep_wfrag(const float* __restrict__ W1) {
    int flat = blockIdx.x * blockDim.x + threadIdx.x;   // 8192 entries
    if (flat >= 8192) return;
    int j  = flat & 3;
    int l  = (flat >> 2) & 31;
    int pr = (flat >> 7) & 3;
    int ks = (flat >> 9) & 7;
    int nb = (flat >> 12) & 1;
    int n = nb * 64 + pr * 16 + ((j >> 1) << 3) + (l >> 2);
    int k = ks * 16 + ((j & 1) << 3) + 2 * (l & 3);
    g_Wfrag[flat] = pack_h2(__float2half_rn(W1[n * 128 + k]),
                            __float2half_rn(W1[n * 128 + k + 1]));
}

__global__ __launch_bounds__(NTHREADS, 2)
void pipnet_hmma_kernel(const float* __restrict__ g1,
                        const float* __restrict__ g2,
                        const int* __restrict__ idxL,
                        const int* __restrict__ idxR,
                        const float* __restrict__ b1,
                        const float* __restrict__ W2,
                        const float* __restrict__ b2,
                        float* __restrict__ out,
                        int P, int Nnodes)
{
    extern __shared__ char smem[];
    const uint32_t sbase = smem_u32(smem);
    const int tid = threadIdx.x;
    const int wid = tid >> 5;
    const int lid = tid & 31;
    const long long base = (long long)blockIdx.x * MTILE;

    // ---- Stage b1 / W2 ----
    if (tid < 128) {
        *(float*)(smem + SM_B1 + tid * 4) = b1[tid];
        *(float*)(smem + SM_W2 + tid * 4) = W2[tid];
    }

    // ---- Coalesced gather: 16 lanes per node row, single fp16 ----
    // 256 row-halves: rh in [0,256), r = rh & 127 (pair row), h = rh >> 7.
    {
        const int lane_in = lid & 15;       // float4 position within the row
        #pragma unroll
        for (int i = 0; i < 16; ++i) {
            int rh = wid * 32 + i * 2 + (lid >> 4);
            int r = rh & 127;
            int h = rh >> 7;
            long long pair = base + r;
            if (pair >= P) pair = P - 1;
            int srcRow = h ? idxR[pair] : idxL[pair];
            if (srcRow < 0) srcRow = 0;
            if (srcRow >= Nnodes) srcRow = Nnodes - 1;
            const float4* src =
                (const float4*)((h ? g2 : g1) + (long long)srcRow * 64);
            float4 v = src[lane_in];
            uint2 hv = make_uint2(pack_h2(__float2half_rn(v.x), __float2half_rn(v.y)),
                                  pack_h2(__float2half_rn(v.z), __float2half_rn(v.w)));
            uint32_t off = tile_off(r, h * 8 + (lane_in >> 1)) + (lane_in & 1) * 8;
            *(uint2*)(smem + SM_A + off) = hv;
        }
    }
    __syncthreads();

    // ---- HMMA mainloop: warp = 32m x 64n ----
    const int m_base = (wid >> 1) * 32;
    const int nb = wid & 1;
    const int n_base = nb * 64;
    const int gl = lid & 7;
    const int grp = lid >> 3;

    float acc[2][8][4];
    #pragma unroll
    for (int mt = 0; mt < 2; ++mt)
        #pragma unroll
        for (int c = 0; c < 8; ++c)
            #pragma unroll
            for (int q = 0; q < 4; ++q) acc[mt][c][q] = 0.f;

    const uint32_t aT = sbase + SM_A;
    const uint4* __restrict__ Wf = (const uint4*)g_Wfrag;

    #pragma unroll
    for (int ks = 0; ks < 8; ++ks) {
        int kc = ks * 2;
        // A frags: 2 subtiles of 16 rows (2 LDSM.x4)
        uint32_t af[2][4];
        #pragma unroll
        for (int mt = 0; mt < 2; ++mt) {
            int row = m_base + mt * 16 + (grp & 1) * 8 + gl;
            ldsm_x4(af[mt], aT + tile_off(row, kc + (grp >> 1)));
        }
        // B frags: 4 LDG.128 (one per pr) serving both m subtiles
        const uint4* wk = Wf + ((nb * 8 + ks) * 4) * 32 + lid;
        #pragma unroll
        for (int pr = 0; pr < 4; ++pr) {
            uint4 vb = wk[pr * 32];
            #pragma unroll
            for (int mt = 0; mt < 2; ++mt) {
                mma_f16(acc[mt][pr * 2],     af[mt], vb.x, vb.y);
                mma_f16(acc[mt][pr * 2 + 1], af[mt], vb.z, vb.w);
            }
        }
    }

    // ---- Epilogue: bias + ReLU + W2 dot from accumulators ----
    const float* s_b1 = (const float*)(smem + SM_B1);
    const float* s_w2 = (const float*)(smem + SM_W2);
    float* red = (float*)(smem + SM_RED);
    const int q2 = (lid & 3) * 2;

    float b1v[8][2], w2v[8][2];
    #pragma unroll
    for (int c = 0; c < 8; ++c) {
        int n = n_base + c * 8 + q2;
        b1v[c][0] = s_b1[n];     b1v[c][1] = s_b1[n + 1];
        w2v[c][0] = s_w2[n];     w2v[c][1] = s_w2[n + 1];
    }

    #pragma unroll
    for (int mt = 0; mt < 2; ++mt) {
        float pa = 0.f, pb = 0.f;   // rows m_base+mt*16+(lid>>2) and +8
        #pragma unroll
        for (int c = 0; c < 8; ++c) {
            pa += fmaxf(acc[mt][c][0] + b1v[c][0], 0.f) * w2v[c][0]
                + fmaxf(acc[mt][c][1] + b1v[c][1], 0.f) * w2v[c][1];
            pb += fmaxf(acc[mt][c][2] + b1v[c][0], 0.f) * w2v[c][0]
                + fmaxf(acc[mt][c][3] + b1v[c][1], 0.f) * w2v[c][1];
        }
        pa += __shfl_xor_sync(0xffffffffu, pa, 1);
        pa += __shfl_xor_sync(0xffffffffu, pa, 2);
        pb += __shfl_xor_sync(0xffffffffu, pb, 1);
        pb += __shfl_xor_sync(0xffffffffu, pb, 2);
        if ((lid & 3) == 0) {
            int ra = m_base + mt * 16 + (lid >> 2);
            red[ra * 2 + nb] = pa;
            red[(ra + 8) * 2 + nb] = pb;
        }
    }
    __syncthreads();

    if (tid < MTILE) {
        float s = red[tid * 2] + red[tid * 2 + 1] + b2[0];
        long long p = base + tid;
        if (p < P) out[p] = s;
    }
}

extern "C" void kernel_launch(void* const* d_in, const int* in_sizes, int n_in,
                              void* d_out, int out_size) {
    const float* g1  = (const float*)d_in[0];   // graph1_x [N,64]
    const float* g2  = (const float*)d_in[1];   // graph2_x [N,64]
    const int*   il  = (const int*)d_in[2];     // idx_left  [P] int32
    const int*   ir  = (const int*)d_in[3];     // idx_right [P] int32
    const float* W1  = (const float*)d_in[4];   // [128,128]
    const float* b1  = (const float*)d_in[5];   // [128]
    const float* W2  = (const float*)d_in[6];   // [1,128]
    const float* b2  = (const float*)d_in[7];   // [1]
    float*       out = (float*)d_out;           // [P,1]

    int P = in_sizes[2];
    int Nnodes = in_sizes[0] / 64;
    int grid = (P + MTILE - 1) / MTILE;

    pipnet_prep_wfrag<<<32, 256>>>(W1);

    cudaFuncSetAttribute(pipnet_hmma_kernel,
                         cudaFuncAttributeMaxDynamicSharedMemorySize, SMEM_TOTAL);
    pipnet_hmma_kernel<<<grid, NTHREADS, SMEM_TOTAL>>>(
        g1, g2, il, ir, b1, W2, b2, out, P, Nnodes);
}